// round 6
// baseline (speedup 1.0000x reference)
#include <cuda_runtime.h>
#include <cstdint>

// Problem constants
#define BB 4
#define LL 2048
#define DM 1024
#define DS 64
#define DI 2048
#define KC 4
#define BL (BB * LL)          // 8192
#define NPROJ 512             // 2 proj * 4 taps * 64 states
#define NCHUNK 32
#define CLEN 64               // NCHUNK * CLEN = LL

// ---------------------------------------------------------------------------
// Scratch: one big __device__ array, offsets in floats
// ---------------------------------------------------------------------------
#define OFF_APRIME   0                         // 512*2048
#define OFF_MPART    (OFF_APRIME + 512*2048)   // 8*512*1024
#define OFF_MFULL    (OFF_MPART + 8*512*1024)  // 512*1024
#define OFF_MT       (OFF_MFULL + 512*1024)    // 1024*512
#define OFF_WOT      (OFF_MT + 1024*512)       // 2048*1024
#define OFF_CPART    (OFF_WOT + 2048*1024)     // 16*64*1024
#define OFF_CM       (OFF_CPART + 16*64*1024)  // 64*1024
#define OFF_BIAS0    (OFF_CM + 64*1024)        // 128
#define OFF_TB       (OFF_BIAS0 + 128)         // 512
#define OFF_G        (OFF_TB + 512)            // 8192*512
#define OFF_DA       (OFF_G + 8192*512)        // 8192*64
#define OFF_DBX      (OFF_DA + 8192*64)        // 8192*64
#define OFF_CHA      (OFF_DBX + 8192*64)       // 8192
#define OFF_CHB      (OFF_CHA + 8192)
#define OFF_ZINIT    (OFF_CHB + 8192)
#define OFF_Z        (OFF_ZINIT + 8192)        // 8192*64
#define SCRATCH_TOTAL (OFF_Z + 8192*64)

__device__ __align__(256) float g_scratch[SCRATCH_TOTAL];

// ---------------------------------------------------------------------------
// Classic 128x128x8 register-tiled SGEMM, row-major A[M,K] * B[K,N] -> C[M,N]
// split-K via blockIdx.z (each z writes its own slice C + z*M*N).
// bias (optional) added on store (use only with gridDim.z == 1).
// Requires: K % 8 == 0, N % 128 == 0. M may be arbitrary (guarded).
// ---------------------------------------------------------------------------
__global__ __launch_bounds__(256) void sgemm128(
    const float* __restrict__ A, const float* __restrict__ B,
    float* __restrict__ C, const float* __restrict__ bias,
    int M, int N, int K, int kChunk)
{
    __shared__ float As[8][128];
    __shared__ float Bs[8][128];
    const int tid = threadIdx.x;
    const int bm = blockIdx.y * 128;
    const int bn = blockIdx.x * 128;
    const int k0 = blockIdx.z * kChunk;

    const int aRow = tid >> 1;          // 0..127
    const int aCol = (tid & 1) << 2;    // 0 or 4
    const int bRow = tid >> 5;          // 0..7
    const int bCol = (tid & 31) << 2;   // 0..124

    const int r0 = (tid >> 4) << 2;     // 0..60
    const int c0 = (tid & 15) << 2;     // 0..60

    float acc[8][8];
#pragma unroll
    for (int i = 0; i < 8; i++)
#pragma unroll
        for (int j = 0; j < 8; j++) acc[i][j] = 0.f;

    const bool aValid = (bm + aRow) < M;
    const float* Aptr = A + (size_t)(bm + aRow) * K + aCol;

    for (int k = k0; k < k0 + kChunk; k += 8) {
        float4 av = aValid ? *reinterpret_cast<const float4*>(Aptr + k)
                           : make_float4(0.f, 0.f, 0.f, 0.f);
        As[aCol + 0][aRow] = av.x;
        As[aCol + 1][aRow] = av.y;
        As[aCol + 2][aRow] = av.z;
        As[aCol + 3][aRow] = av.w;
        float4 bv = *reinterpret_cast<const float4*>(&B[(size_t)(k + bRow) * N + bn + bCol]);
        *reinterpret_cast<float4*>(&Bs[bRow][bCol]) = bv;
        __syncthreads();
#pragma unroll
        for (int kk = 0; kk < 8; kk++) {
            float4 a0 = *reinterpret_cast<const float4*>(&As[kk][r0]);
            float4 a1 = *reinterpret_cast<const float4*>(&As[kk][r0 + 64]);
            float4 b0 = *reinterpret_cast<const float4*>(&Bs[kk][c0]);
            float4 b1 = *reinterpret_cast<const float4*>(&Bs[kk][c0 + 64]);
            float ar[8] = {a0.x, a0.y, a0.z, a0.w, a1.x, a1.y, a1.z, a1.w};
            float br[8] = {b0.x, b0.y, b0.z, b0.w, b1.x, b1.y, b1.z, b1.w};
#pragma unroll
            for (int i = 0; i < 8; i++)
#pragma unroll
                for (int j = 0; j < 8; j++) acc[i][j] += ar[i] * br[j];
        }
        __syncthreads();
    }

    float* Cout = C + (size_t)blockIdx.z * M * N;
#pragma unroll
    for (int ih = 0; ih < 2; ih++)
#pragma unroll
        for (int i = 0; i < 4; i++) {
            int row = bm + r0 + ih * 64 + i;
            if (row < M) {
#pragma unroll
                for (int jh = 0; jh < 2; jh++) {
                    int col = bn + c0 + jh * 64;
                    float4 v;
                    v.x = acc[ih * 4 + i][jh * 4 + 0];
                    v.y = acc[ih * 4 + i][jh * 4 + 1];
                    v.z = acc[ih * 4 + i][jh * 4 + 2];
                    v.w = acc[ih * 4 + i][jh * 4 + 3];
                    if (bias) {
                        v.x += bias[col + 0];
                        v.y += bias[col + 1];
                        v.z += bias[col + 2];
                        v.w += bias[col + 3];
                    }
                    *reinterpret_cast<float4*>(&Cout[(size_t)row * N + col]) = v;
                }
            }
        }
}

// ---------------------------------------------------------------------------
// Reduce split-K partials: out[idx] = sum_s parts[s*total + idx]
// ---------------------------------------------------------------------------
__global__ void reduce_kernel(const float* __restrict__ parts, float* __restrict__ out,
                              int total, int S)
{
    int idx = blockIdx.x * blockDim.x + threadIdx.x;
    if (idx >= total) return;
    float s = 0.f;
    for (int i = 0; i < S; i++) s += parts[(size_t)i * total + idx];
    out[idx] = s;
}

// ---------------------------------------------------------------------------
// Tiled transpose: in[R][Cc] -> out[Cc][R]
// ---------------------------------------------------------------------------
__global__ void transpose_kernel(const float* __restrict__ in, float* __restrict__ out,
                                 int R, int Cc)
{
    __shared__ float tile[32][33];
    int c = blockIdx.x * 32 + threadIdx.x;
    int r = blockIdx.y * 32 + threadIdx.y;
#pragma unroll
    for (int j = 0; j < 4; j++) {
        int rr = r + j * 8;
        if (rr < R && c < Cc) tile[threadIdx.y + j * 8][threadIdx.x] = in[(size_t)rr * Cc + c];
    }
    __syncthreads();
    int c2 = blockIdx.y * 32 + threadIdx.x;   // output col = original row
    int r2 = blockIdx.x * 32 + threadIdx.y;   // output row = original col
#pragma unroll
    for (int j = 0; j < 4; j++) {
        int rr = r2 + j * 8;
        if (rr < Cc && c2 < R) out[(size_t)rr * R + c2] = tile[threadIdx.x][threadIdx.y + j * 8];
    }
}

// ---------------------------------------------------------------------------
// A'[r][i] = W_P[s][i] * conv_w[i][k],  r = P*256 + k*64 + s
// ---------------------------------------------------------------------------
__global__ void build_aprime(const float* __restrict__ W_x, const float* __restrict__ W_dt,
                             const float* __restrict__ conv_w, float* __restrict__ Ap)
{
    int idx = blockIdx.x * blockDim.x + threadIdx.x;   // 512 * 2048
    int i = idx & (DI - 1);
    int r = idx >> 11;
    int P = r >> 8;
    int k = (r >> 6) & 3;
    int s = r & 63;
    const float* W = P ? W_dt : W_x;
    Ap[idx] = W[(size_t)s * DI + i] * conv_w[i * KC + k];
}

// ---------------------------------------------------------------------------
// Bias terms: bias0[P*64+s] = b_P[s] + sum_i W_P[s,i]*conv_b[i]
//             tb[(P*4+k)*64+s] = sum_i W_P[s,i]*conv_w[i,k]*b_in[i]
// One warp per output.
// ---------------------------------------------------------------------------
__global__ void bias_kernel(const float* __restrict__ W_x, const float* __restrict__ W_dt,
                            const float* __restrict__ b_x, const float* __restrict__ b_dt,
                            const float* __restrict__ conv_w, const float* __restrict__ conv_b,
                            const float* __restrict__ b_in,
                            float* __restrict__ bias0, float* __restrict__ tb)
{
    int warpId = blockIdx.x * (blockDim.x >> 5) + (threadIdx.x >> 5);
    int lane = threadIdx.x & 31;
    if (warpId < 128) {
        int P = warpId >> 6, s = warpId & 63;
        const float* W = P ? W_dt : W_x;
        float sum = 0.f;
        for (int i = lane; i < DI; i += 32) sum += W[(size_t)s * DI + i] * conv_b[i];
#pragma unroll
        for (int o = 16; o; o >>= 1) sum += __shfl_xor_sync(0xffffffffu, sum, o);
        if (lane == 0) bias0[P * 64 + s] = sum + (P ? b_dt[s] : b_x[s]);
    } else if (warpId < 640) {
        int w2 = warpId - 128;
        int P = w2 >> 8, k = (w2 >> 6) & 3, s = w2 & 63;
        const float* W = P ? W_dt : W_x;
        float sum = 0.f;
        for (int i = lane; i < DI; i += 32)
            sum += W[(size_t)s * DI + i] * conv_w[i * KC + k] * b_in[i];
#pragma unroll
        for (int o = 16; o; o >>= 1) sum += __shfl_xor_sync(0xffffffffu, sum, o);
        if (lane == 0) tb[(P * 4 + k) * 64 + s] = sum;
    }
}

// ---------------------------------------------------------------------------
// Combine taps + SSM elementwise: builds dA, dBx arrays [B,L,64]
// ---------------------------------------------------------------------------
__global__ void combine_kernel(const float* __restrict__ G, const float* __restrict__ bias0,
                               const float* __restrict__ tb, const float* __restrict__ A_log,
                               float* __restrict__ dAo, float* __restrict__ dBxo)
{
    int idx = blockIdx.x * blockDim.x + threadIdx.x;   // B*L*64
    int s = idx & 63;
    int bl = idx >> 6;                 // b*L + l
    int l = bl & (LL - 1);
    int b = bl >> 11;
    float xs = bias0[s];
    float dtp = bias0[64 + s];
#pragma unroll
    for (int k = 0; k < 4; k++) {
        int t = l - 3 + k;
        if (t >= 0) {
            const float* g = G + (size_t)(b * LL + t) * NPROJ + k * 64 + s;
            xs  += g[0]   + tb[k * 64 + s];
            dtp += g[256] + tb[256 + k * 64 + s];
        }
    }
    float dt = (dtp > 20.f) ? dtp : log1pf(expf(dtp));
    float Aval = -expf(A_log[s]);
    float da = expf(Aval * dt);
    dAo[idx] = da;
    dBxo[idx] = (1.f - da) / Aval * xs;
}

// ---------------------------------------------------------------------------
// Chunked parallel scan. Phase 1: per-chunk composition (a, b).
// ---------------------------------------------------------------------------
__global__ void scan_phase1(const float* __restrict__ dA, const float* __restrict__ dBx,
                            float* __restrict__ chA, float* __restrict__ chB)
{
    int b = blockIdx.x;      // batch
    int c = blockIdx.y;      // chunk
    int s = threadIdx.x;     // state (blockDim = 64)
    float a = 1.f, bc = 0.f;
    size_t base = ((size_t)b * LL + (size_t)c * CLEN) * DS + s;
#pragma unroll 4
    for (int t = 0; t < CLEN; t++) {
        float da = dA[base + (size_t)t * DS];
        float dx = dBx[base + (size_t)t * DS];
        a *= da;
        bc = da * bc + dx;
    }
    chA[((size_t)b * DS + s) * NCHUNK + c] = a;
    chB[((size_t)b * DS + s) * NCHUNK + c] = bc;
}

// Phase 2: exclusive scan over chunk summaries (one block, 256 threads = B*DS)
__global__ void scan_phase2(const float* __restrict__ chA, const float* __restrict__ chB,
                            float* __restrict__ zinit)
{
    int tid = threadIdx.x;           // 0..255
    size_t base = (size_t)tid * NCHUNK;
    float z = 0.f;
#pragma unroll
    for (int c = 0; c < NCHUNK; c++) {
        zinit[base + c] = z;
        z = chA[base + c] * z + chB[base + c];
    }
}

// Phase 3: recompute local scans with chunk-initial state, write z[B,L,64]
__global__ void scan_phase3(const float* __restrict__ dA, const float* __restrict__ dBx,
                            const float* __restrict__ zinit, float* __restrict__ Z)
{
    int b = blockIdx.x;
    int c = blockIdx.y;
    int s = threadIdx.x;
    float z = zinit[((size_t)b * DS + s) * NCHUNK + c];
    size_t base = ((size_t)b * LL + (size_t)c * CLEN) * DS + s;
#pragma unroll 4
    for (int t = 0; t < CLEN; t++) {
        size_t o = base + (size_t)t * DS;
        z = dA[o] * z + dBx[o];
        Z[o] = z;
    }
}

// ---------------------------------------------------------------------------
// kernel_launch
// ---------------------------------------------------------------------------
extern "C" void kernel_launch(void* const* d_in, const int* in_sizes, int n_in,
                              void* d_out, int out_size)
{
    (void)in_sizes; (void)n_in; (void)out_size;
    const float* x      = (const float*)d_in[0];
    const float* W_in   = (const float*)d_in[1];
    const float* b_in   = (const float*)d_in[2];
    const float* conv_w = (const float*)d_in[3];
    const float* conv_b = (const float*)d_in[4];
    const float* W_x    = (const float*)d_in[5];
    const float* b_x    = (const float*)d_in[6];
    const float* W_dt   = (const float*)d_in[7];
    const float* b_dt   = (const float*)d_in[8];
    const float* A_log  = (const float*)d_in[9];
    const float* D_mat  = (const float*)d_in[10];
    const float* W_out  = (const float*)d_in[11];
    const float* b_out  = (const float*)d_in[12];
    float* out = (float*)d_out;

    float* scratch = nullptr;
    cudaGetSymbolAddress((void**)&scratch, g_scratch);
    float* Aprime = scratch + OFF_APRIME;
    float* Mpart  = scratch + OFF_MPART;
    float* Mfull  = scratch + OFF_MFULL;
    float* Mt     = scratch + OFF_MT;
    float* WoT    = scratch + OFF_WOT;
    float* Cpart  = scratch + OFF_CPART;
    float* Cm     = scratch + OFF_CM;
    float* bias0  = scratch + OFF_BIAS0;
    float* tb     = scratch + OFF_TB;
    float* G      = scratch + OFF_G;
    float* dAarr  = scratch + OFF_DA;
    float* dBxarr = scratch + OFF_DBX;
    float* chA    = scratch + OFF_CHA;
    float* chB    = scratch + OFF_CHB;
    float* zinit  = scratch + OFF_ZINIT;
    float* Zarr   = scratch + OFF_Z;

    // --- Critical path first: Aprime -> M -> Mt -> G ---
    // 1. A'[512,2048]
    build_aprime<<<(NPROJ * DI) / 256, 256>>>(W_x, W_dt, conv_w, Aprime);

    // 2. M[512,1024] = A' @ W_in   (split-K 8)
    sgemm128<<<dim3(DM / 128, NPROJ / 128, 8), 256>>>(
        Aprime, W_in, Mpart, nullptr, NPROJ, DM, DI, DI / 8);
    reduce_kernel<<<(NPROJ * DM) / 256, 256>>>(Mpart, Mfull, NPROJ * DM, 8);

    // 3. Mt[1024,512] = M^T
    transpose_kernel<<<dim3(DM / 32, NPROJ / 32), dim3(32, 8)>>>(Mfull, Mt, NPROJ, DM);

    // 4. Main GEMM: G[8192,512] = X @ Mt   (the heavy launch)
    sgemm128<<<dim3(NPROJ / 128, BL / 128, 1), 256>>>(
        x, Mt, G, nullptr, BL, NPROJ, DM, DM);

    // --- Off-critical-path setup (stream-ordered after G, cheap) ---
    // 5. WoT[2048,1024] = W_out^T
    transpose_kernel<<<dim3(DI / 32, DM / 32), dim3(32, 8)>>>(W_out, WoT, DM, DI);

    // 6. Cm[64,1024] = D_mat @ WoT  (split-K 16)
    sgemm128<<<dim3(DM / 128, 1, 16), 256>>>(
        D_mat, WoT, Cpart, nullptr, DS, DM, DI, DI / 16);
    reduce_kernel<<<(DS * DM) / 256, 256>>>(Cpart, Cm, DS * DM, 16);

    // 7. bias terms
    bias_kernel<<<80, 256>>>(W_x, W_dt, b_x, b_dt, conv_w, conv_b, b_in, bias0, tb);

    // 8. tap combine + SSM elementwise -> dA, dBx
    combine_kernel<<<(BL * DS) / 256, 256>>>(G, bias0, tb, A_log, dAarr, dBxarr);

    // 9. chunked parallel scan -> Z[8192,64]
    scan_phase1<<<dim3(BB, NCHUNK), DS>>>(dAarr, dBxarr, chA, chB);
    scan_phase2<<<1, BB * DS>>>(chA, chB, zinit);
    scan_phase3<<<dim3(BB, NCHUNK), DS>>>(dAarr, dBxarr, zinit, Zarr);

    // 10. out[8192,1024] = Z @ Cm + b_out
    sgemm128<<<dim3(DM / 128, BL / 128, 1), 256>>>(
        Zarr, Cm, out, b_out, BL, DM, DS, DS);
}

// round 7
// speedup vs baseline: 1.6327x; 1.6327x over previous
#include <cuda_runtime.h>
#include <cuda_bf16.h>
#include <cstdint>

// Problem constants
#define BB 4
#define LL 2048
#define DM 1024
#define DS 64
#define DI 2048
#define KC 4
#define BL (BB * LL)          // 8192
#define NPROJ 512             // 2 proj * 4 taps * 64 states
#define NCHUNK 32
#define CLEN 64               // NCHUNK * CLEN = LL

// ---------------------------------------------------------------------------
// Scratch: one big __device__ array, offsets in floats
// ---------------------------------------------------------------------------
#define OFF_APRIME   0                         // (unused fp32 slot kept for layout stability)
#define OFF_MPART    (OFF_APRIME + 512*2048)   // 8*512*1024
#define OFF_MFULL    (OFF_MPART + 8*512*1024)  // 512*1024
#define OFF_MT       (OFF_MFULL + 512*1024)    // 1024*512
#define OFF_WOT      (OFF_MT + 1024*512)       // 2048*1024
#define OFF_CPART    (OFF_WOT + 2048*1024)     // 16*64*1024
#define OFF_CM       (OFF_CPART + 16*64*1024)  // 64*1024
#define OFF_BIAS0    (OFF_CM + 64*1024)        // 128
#define OFF_TB       (OFF_BIAS0 + 128)         // 512
#define OFF_G        (OFF_TB + 512)            // 8192*512
#define OFF_DA       (OFF_G + 8192*512)        // 8192*64
#define OFF_DBX      (OFF_DA + 8192*64)        // 8192*64
#define OFF_CHA      (OFF_DBX + 8192*64)       // 8192
#define OFF_CHB      (OFF_CHA + 8192)
#define OFF_ZINIT    (OFF_CHB + 8192)
#define OFF_Z        (OFF_ZINIT + 8192)        // 8192*64
// bf16 hi/lo regions (sizes in floats = elems/2)
#define OFF_XHI      (OFF_Z + 8192*64)         // 8192*1024 bf16 = 4M floats
#define OFF_XLO      (OFF_XHI + 4*1024*1024)
#define OFF_WINHI    (OFF_XLO + 4*1024*1024)   // 2048*1024 bf16 = 1M floats
#define OFF_WINLO    (OFF_WINHI + 1024*1024)
#define OFF_APHI     (OFF_WINLO + 1024*1024)   // 512*2048 bf16 = 512K floats
#define OFF_APLO     (OFF_APHI + 512*1024)
#define OFF_MTHI     (OFF_APLO + 512*1024)     // 1024*512 bf16 = 256K floats
#define OFF_MTLO     (OFF_MTHI + 256*1024)
#define OFF_ZHI      (OFF_MTLO + 256*1024)     // 8192*64 bf16 = 256K floats
#define OFF_ZLO      (OFF_ZHI + 256*1024)
#define OFF_CMHI     (OFF_ZLO + 256*1024)      // 64*1024 bf16 = 32K floats
#define OFF_CMLO     (OFF_CMHI + 32*1024)
#define SCRATCH_TOTAL (OFF_CMLO + 32*1024)

__device__ __align__(256) float g_scratch[SCRATCH_TOTAL];

// ---------------------------------------------------------------------------
// MMA helpers (standard sm80+ m16n8k16 bf16 pattern)
// ---------------------------------------------------------------------------
__device__ __forceinline__ uint32_t smem_u32(const void* p) {
    return (uint32_t)__cvta_generic_to_shared(p);
}
__device__ __forceinline__ void ldsm_x4(uint32_t addr, uint32_t& r0, uint32_t& r1,
                                        uint32_t& r2, uint32_t& r3) {
    asm volatile("ldmatrix.sync.aligned.m8n8.x4.shared.b16 {%0,%1,%2,%3}, [%4];"
                 : "=r"(r0), "=r"(r1), "=r"(r2), "=r"(r3) : "r"(addr));
}
__device__ __forceinline__ void ldsm_x2t(uint32_t addr, uint32_t& r0, uint32_t& r1) {
    asm volatile("ldmatrix.sync.aligned.m8n8.x2.trans.shared.b16 {%0,%1}, [%2];"
                 : "=r"(r0), "=r"(r1) : "r"(addr));
}
__device__ __forceinline__ void mma_bf16(float* d, const uint32_t* a, const uint32_t* b) {
    asm volatile("mma.sync.aligned.m16n8k16.row.col.f32.bf16.bf16.f32 "
                 "{%0,%1,%2,%3}, {%4,%5,%6,%7}, {%8,%9}, {%0,%1,%2,%3};"
                 : "+f"(d[0]), "+f"(d[1]), "+f"(d[2]), "+f"(d[3])
                 : "r"(a[0]), "r"(a[1]), "r"(a[2]), "r"(a[3]), "r"(b[0]), "r"(b[1]));
}

// ---------------------------------------------------------------------------
// bf16x3 GEMM: C[M,N] (+bias) = Ahi/lo[M,K] * Bhi/lo[K,N], fp32 accumulate.
// acc = AhBh + AhBl + AlBh  (lo*lo term ~2^-16, dropped).
// Block 128x128, K-step 32, 256 threads (8 warps: 2m x 4n, warp tile 64x32).
// Requires M%128==0, N%128==0, K%32==0, kChunk%32==0.
// split-K via blockIdx.z writing slice C + z*M*N.
// ---------------------------------------------------------------------------
#define AS_STRIDE 40    // 128x32 tile, padded: LDSM 16B reads conflict-free
#define BS_STRIDE 136   // 32x128 tile, padded

__global__ __launch_bounds__(256) void gemm_bf16x3(
    const __nv_bfloat16* __restrict__ Ahi, const __nv_bfloat16* __restrict__ Alo,
    const __nv_bfloat16* __restrict__ Bhi, const __nv_bfloat16* __restrict__ Blo,
    float* __restrict__ C, const float* __restrict__ bias,
    int M, int N, int K, int kChunk)
{
    __shared__ __nv_bfloat16 AsH[128][AS_STRIDE];
    __shared__ __nv_bfloat16 AsL[128][AS_STRIDE];
    __shared__ __nv_bfloat16 BsH[32][BS_STRIDE];
    __shared__ __nv_bfloat16 BsL[32][BS_STRIDE];

    const int tid  = threadIdx.x;
    const int lane = tid & 31;
    const int warp = tid >> 5;
    const int wm   = warp & 1;     // m-offset 64*wm
    const int wn   = warp >> 1;    // n-offset 32*wn
    const int bm   = blockIdx.y * 128;
    const int bn   = blockIdx.x * 128;
    const int kStart = blockIdx.z * kChunk;

    float acc[4][4][4];
#pragma unroll
    for (int i = 0; i < 4; i++)
#pragma unroll
        for (int j = 0; j < 4; j++)
#pragma unroll
            for (int v = 0; v < 4; v++) acc[i][j][v] = 0.f;

    for (int k0 = kStart; k0 < kStart + kChunk; k0 += 32) {
        // A tile: 128 rows x 32 k (hi+lo), 4 bf16 per 8B chunk
#pragma unroll
        for (int i = tid; i < 128 * 8; i += 256) {
            int r = i >> 3, c4 = (i & 7) << 2;
            size_t go = (size_t)(bm + r) * K + k0 + c4;
            *reinterpret_cast<uint2*>(&AsH[r][c4]) =
                *reinterpret_cast<const uint2*>(&Ahi[go]);
            *reinterpret_cast<uint2*>(&AsL[r][c4]) =
                *reinterpret_cast<const uint2*>(&Alo[go]);
        }
        // B tile: 32 k-rows x 128 n (hi+lo)
#pragma unroll
        for (int i = tid; i < 32 * 32; i += 256) {
            int r = i >> 5, c4 = (i & 31) << 2;
            size_t go = (size_t)(k0 + r) * N + bn + c4;
            *reinterpret_cast<uint2*>(&BsH[r][c4]) =
                *reinterpret_cast<const uint2*>(&Bhi[go]);
            *reinterpret_cast<uint2*>(&BsL[r][c4]) =
                *reinterpret_cast<const uint2*>(&Blo[go]);
        }
        __syncthreads();

#pragma unroll
        for (int kt = 0; kt < 2; kt++) {
            uint32_t aH[4][4], aL[4][4], bH[4][2], bL[4][2];
            const int arow = lane & 15;
            const int acol = kt * 16 + (lane >> 4) * 8;
#pragma unroll
            for (int mf = 0; mf < 4; mf++) {
                int m0 = wm * 64 + mf * 16 + arow;
                ldsm_x4(smem_u32(&AsH[m0][acol]), aH[mf][0], aH[mf][1], aH[mf][2], aH[mf][3]);
                ldsm_x4(smem_u32(&AsL[m0][acol]), aL[mf][0], aL[mf][1], aL[mf][2], aL[mf][3]);
            }
            const int brow = kt * 16 + (lane & 15);
#pragma unroll
            for (int nf = 0; nf < 4; nf++) {
                int n0 = wn * 32 + nf * 8;
                ldsm_x2t(smem_u32(&BsH[brow][n0]), bH[nf][0], bH[nf][1]);
                ldsm_x2t(smem_u32(&BsL[brow][n0]), bL[nf][0], bL[nf][1]);
            }
#pragma unroll
            for (int mf = 0; mf < 4; mf++)
#pragma unroll
                for (int nf = 0; nf < 4; nf++) {
                    mma_bf16(acc[mf][nf], aH[mf], bH[nf]);
                    mma_bf16(acc[mf][nf], aH[mf], bL[nf]);
                    mma_bf16(acc[mf][nf], aL[mf], bH[nf]);
                }
        }
        __syncthreads();
    }

    // Epilogue
    const int g = lane >> 2, t = lane & 3;
    float* Cout = C + (size_t)blockIdx.z * M * N;
#pragma unroll
    for (int mf = 0; mf < 4; mf++) {
#pragma unroll
        for (int nf = 0; nf < 4; nf++) {
            int row = bm + wm * 64 + mf * 16 + g;
            int col = bn + wn * 32 + nf * 8 + 2 * t;
            float b0v = 0.f, b1v = 0.f;
            if (bias) { b0v = bias[col]; b1v = bias[col + 1]; }
            float2 v;
            v.x = acc[mf][nf][0] + b0v; v.y = acc[mf][nf][1] + b1v;
            *reinterpret_cast<float2*>(&Cout[(size_t)row * N + col]) = v;
            v.x = acc[mf][nf][2] + b0v; v.y = acc[mf][nf][3] + b1v;
            *reinterpret_cast<float2*>(&Cout[(size_t)(row + 8) * N + col]) = v;
        }
    }
}

// ---------------------------------------------------------------------------
// fp32 -> (bf16 hi, bf16 lo) split:  hi = bf16(v), lo = bf16(v - hi)
// ---------------------------------------------------------------------------
__global__ void f32_to_bf16x2(const float* __restrict__ src,
                              __nv_bfloat16* __restrict__ hi,
                              __nv_bfloat16* __restrict__ lo, int n)
{
    int idx = blockIdx.x * blockDim.x + threadIdx.x;
    if (idx >= n) return;
    float v = src[idx];
    __nv_bfloat16 h = __float2bfloat16_rn(v);
    hi[idx] = h;
    lo[idx] = __float2bfloat16_rn(v - __bfloat162float(h));
}

// ---------------------------------------------------------------------------
// Classic 128x128x8 register-tiled fp32 SGEMM (kept for the small Cm GEMM).
// ---------------------------------------------------------------------------
__global__ __launch_bounds__(256) void sgemm128(
    const float* __restrict__ A, const float* __restrict__ B,
    float* __restrict__ C, const float* __restrict__ bias,
    int M, int N, int K, int kChunk)
{
    __shared__ float As[8][128];
    __shared__ float Bs[8][128];
    const int tid = threadIdx.x;
    const int bm = blockIdx.y * 128;
    const int bn = blockIdx.x * 128;
    const int k0 = blockIdx.z * kChunk;

    const int aRow = tid >> 1;
    const int aCol = (tid & 1) << 2;
    const int bRow = tid >> 5;
    const int bCol = (tid & 31) << 2;
    const int r0 = (tid >> 4) << 2;
    const int c0 = (tid & 15) << 2;

    float acc[8][8];
#pragma unroll
    for (int i = 0; i < 8; i++)
#pragma unroll
        for (int j = 0; j < 8; j++) acc[i][j] = 0.f;

    const bool aValid = (bm + aRow) < M;
    const float* Aptr = A + (size_t)(bm + aRow) * K + aCol;

    for (int k = k0; k < k0 + kChunk; k += 8) {
        float4 av = aValid ? *reinterpret_cast<const float4*>(Aptr + k)
                           : make_float4(0.f, 0.f, 0.f, 0.f);
        As[aCol + 0][aRow] = av.x;
        As[aCol + 1][aRow] = av.y;
        As[aCol + 2][aRow] = av.z;
        As[aCol + 3][aRow] = av.w;
        float4 bv = *reinterpret_cast<const float4*>(&B[(size_t)(k + bRow) * N + bn + bCol]);
        *reinterpret_cast<float4*>(&Bs[bRow][bCol]) = bv;
        __syncthreads();
#pragma unroll
        for (int kk = 0; kk < 8; kk++) {
            float4 a0 = *reinterpret_cast<const float4*>(&As[kk][r0]);
            float4 a1 = *reinterpret_cast<const float4*>(&As[kk][r0 + 64]);
            float4 b0 = *reinterpret_cast<const float4*>(&Bs[kk][c0]);
            float4 b1 = *reinterpret_cast<const float4*>(&Bs[kk][c0 + 64]);
            float ar[8] = {a0.x, a0.y, a0.z, a0.w, a1.x, a1.y, a1.z, a1.w};
            float br[8] = {b0.x, b0.y, b0.z, b0.w, b1.x, b1.y, b1.z, b1.w};
#pragma unroll
            for (int i = 0; i < 8; i++)
#pragma unroll
                for (int j = 0; j < 8; j++) acc[i][j] += ar[i] * br[j];
        }
        __syncthreads();
    }

    float* Cout = C + (size_t)blockIdx.z * M * N;
#pragma unroll
    for (int ih = 0; ih < 2; ih++)
#pragma unroll
        for (int i = 0; i < 4; i++) {
            int row = bm + r0 + ih * 64 + i;
            if (row < M) {
#pragma unroll
                for (int jh = 0; jh < 2; jh++) {
                    int col = bn + c0 + jh * 64;
                    float4 v;
                    v.x = acc[ih * 4 + i][jh * 4 + 0];
                    v.y = acc[ih * 4 + i][jh * 4 + 1];
                    v.z = acc[ih * 4 + i][jh * 4 + 2];
                    v.w = acc[ih * 4 + i][jh * 4 + 3];
                    if (bias) {
                        v.x += bias[col + 0];
                        v.y += bias[col + 1];
                        v.z += bias[col + 2];
                        v.w += bias[col + 3];
                    }
                    *reinterpret_cast<float4*>(&Cout[(size_t)row * N + col]) = v;
                }
            }
        }
}

__global__ void reduce_kernel(const float* __restrict__ parts, float* __restrict__ out,
                              int total, int S)
{
    int idx = blockIdx.x * blockDim.x + threadIdx.x;
    if (idx >= total) return;
    float s = 0.f;
    for (int i = 0; i < S; i++) s += parts[(size_t)i * total + idx];
    out[idx] = s;
}

__global__ void transpose_kernel(const float* __restrict__ in, float* __restrict__ out,
                                 int R, int Cc)
{
    __shared__ float tile[32][33];
    int c = blockIdx.x * 32 + threadIdx.x;
    int r = blockIdx.y * 32 + threadIdx.y;
#pragma unroll
    for (int j = 0; j < 4; j++) {
        int rr = r + j * 8;
        if (rr < R && c < Cc) tile[threadIdx.y + j * 8][threadIdx.x] = in[(size_t)rr * Cc + c];
    }
    __syncthreads();
    int c2 = blockIdx.y * 32 + threadIdx.x;
    int r2 = blockIdx.x * 32 + threadIdx.y;
#pragma unroll
    for (int j = 0; j < 4; j++) {
        int rr = r2 + j * 8;
        if (rr < Cc && c2 < R) out[(size_t)rr * R + c2] = tile[threadIdx.x][threadIdx.y + j * 8];
    }
}

// A'[r][i] = W_P[s][i]*conv_w[i][k] emitted directly as bf16 hi/lo
__global__ void build_aprime_bf16(const float* __restrict__ W_x, const float* __restrict__ W_dt,
                                  const float* __restrict__ conv_w,
                                  __nv_bfloat16* __restrict__ hi, __nv_bfloat16* __restrict__ lo)
{
    int idx = blockIdx.x * blockDim.x + threadIdx.x;   // 512*2048
    int i = idx & (DI - 1);
    int r = idx >> 11;
    int P = r >> 8;
    int k = (r >> 6) & 3;
    int s = r & 63;
    const float* W = P ? W_dt : W_x;
    float v = W[(size_t)s * DI + i] * conv_w[i * KC + k];
    __nv_bfloat16 h = __float2bfloat16_rn(v);
    hi[idx] = h;
    lo[idx] = __float2bfloat16_rn(v - __bfloat162float(h));
}

__global__ void bias_kernel(const float* __restrict__ W_x, const float* __restrict__ W_dt,
                            const float* __restrict__ b_x, const float* __restrict__ b_dt,
                            const float* __restrict__ conv_w, const float* __restrict__ conv_b,
                            const float* __restrict__ b_in,
                            float* __restrict__ bias0, float* __restrict__ tb)
{
    int warpId = blockIdx.x * (blockDim.x >> 5) + (threadIdx.x >> 5);
    int lane = threadIdx.x & 31;
    if (warpId < 128) {
        int P = warpId >> 6, s = warpId & 63;
        const float* W = P ? W_dt : W_x;
        float sum = 0.f;
        for (int i = lane; i < DI; i += 32) sum += W[(size_t)s * DI + i] * conv_b[i];
#pragma unroll
        for (int o = 16; o; o >>= 1) sum += __shfl_xor_sync(0xffffffffu, sum, o);
        if (lane == 0) bias0[P * 64 + s] = sum + (P ? b_dt[s] : b_x[s]);
    } else if (warpId < 640) {
        int w2 = warpId - 128;
        int P = w2 >> 8, k = (w2 >> 6) & 3, s = w2 & 63;
        const float* W = P ? W_dt : W_x;
        float sum = 0.f;
        for (int i = lane; i < DI; i += 32)
            sum += W[(size_t)s * DI + i] * conv_w[i * KC + k] * b_in[i];
#pragma unroll
        for (int o = 16; o; o >>= 1) sum += __shfl_xor_sync(0xffffffffu, sum, o);
        if (lane == 0) tb[(P * 4 + k) * 64 + s] = sum;
    }
}

__global__ void combine_kernel(const float* __restrict__ G, const float* __restrict__ bias0,
                               const float* __restrict__ tb, const float* __restrict__ A_log,
                               float* __restrict__ dAo, float* __restrict__ dBxo)
{
    int idx = blockIdx.x * blockDim.x + threadIdx.x;   // B*L*64
    int s = idx & 63;
    int bl = idx >> 6;
    int l = bl & (LL - 1);
    int b = bl >> 11;
    float xs = bias0[s];
    float dtp = bias0[64 + s];
#pragma unroll
    for (int k = 0; k < 4; k++) {
        int t = l - 3 + k;
        if (t >= 0) {
            const float* g = G + (size_t)(b * LL + t) * NPROJ + k * 64 + s;
            xs  += g[0]   + tb[k * 64 + s];
            dtp += g[256] + tb[256 + k * 64 + s];
        }
    }
    float dt = (dtp > 20.f) ? dtp : log1pf(expf(dtp));
    float Aval = -expf(A_log[s]);
    float da = expf(Aval * dt);
    dAo[idx] = da;
    dBxo[idx] = (1.f - da) / Aval * xs;
}

__global__ void scan_phase1(const float* __restrict__ dA, const float* __restrict__ dBx,
                            float* __restrict__ chA, float* __restrict__ chB)
{
    int b = blockIdx.x;
    int c = blockIdx.y;
    int s = threadIdx.x;
    float a = 1.f, bc = 0.f;
    size_t base = ((size_t)b * LL + (size_t)c * CLEN) * DS + s;
#pragma unroll 4
    for (int t = 0; t < CLEN; t++) {
        float da = dA[base + (size_t)t * DS];
        float dx = dBx[base + (size_t)t * DS];
        a *= da;
        bc = da * bc + dx;
    }
    chA[((size_t)b * DS + s) * NCHUNK + c] = a;
    chB[((size_t)b * DS + s) * NCHUNK + c] = bc;
}

__global__ void scan_phase2(const float* __restrict__ chA, const float* __restrict__ chB,
                            float* __restrict__ zinit)
{
    int tid = threadIdx.x;
    size_t base = (size_t)tid * NCHUNK;
    float z = 0.f;
#pragma unroll
    for (int c = 0; c < NCHUNK; c++) {
        zinit[base + c] = z;
        z = chA[base + c] * z + chB[base + c];
    }
}

__global__ void scan_phase3(const float* __restrict__ dA, const float* __restrict__ dBx,
                            const float* __restrict__ zinit, float* __restrict__ Z)
{
    int b = blockIdx.x;
    int c = blockIdx.y;
    int s = threadIdx.x;
    float z = zinit[((size_t)b * DS + s) * NCHUNK + c];
    size_t base = ((size_t)b * LL + (size_t)c * CLEN) * DS + s;
#pragma unroll 4
    for (int t = 0; t < CLEN; t++) {
        size_t o = base + (size_t)t * DS;
        z = dA[o] * z + dBx[o];
        Z[o] = z;
    }
}

// ---------------------------------------------------------------------------
// kernel_launch
// ---------------------------------------------------------------------------
extern "C" void kernel_launch(void* const* d_in, const int* in_sizes, int n_in,
                              void* d_out, int out_size)
{
    (void)in_sizes; (void)n_in; (void)out_size;
    const float* x      = (const float*)d_in[0];
    const float* W_in   = (const float*)d_in[1];
    const float* b_in   = (const float*)d_in[2];
    const float* conv_w = (const float*)d_in[3];
    const float* conv_b = (const float*)d_in[4];
    const float* W_x    = (const float*)d_in[5];
    const float* b_x    = (const float*)d_in[6];
    const float* W_dt   = (const float*)d_in[7];
    const float* b_dt   = (const float*)d_in[8];
    const float* A_log  = (const float*)d_in[9];
    const float* D_mat  = (const float*)d_in[10];
    const float* W_out  = (const float*)d_in[11];
    const float* b_out  = (const float*)d_in[12];
    float* out = (float*)d_out;

    float* scratch = nullptr;
    cudaGetSymbolAddress((void**)&scratch, g_scratch);
    float* Mpart  = scratch + OFF_MPART;
    float* Mfull  = scratch + OFF_MFULL;
    float* Mt     = scratch + OFF_MT;
    float* WoT    = scratch + OFF_WOT;
    float* Cpart  = scratch + OFF_CPART;
    float* Cm     = scratch + OFF_CM;
    float* bias0  = scratch + OFF_BIAS0;
    float* tb     = scratch + OFF_TB;
    float* G      = scratch + OFF_G;
    float* dAarr  = scratch + OFF_DA;
    float* dBxarr = scratch + OFF_DBX;
    float* chA    = scratch + OFF_CHA;
    float* chB    = scratch + OFF_CHB;
    float* zinit  = scratch + OFF_ZINIT;
    float* Zarr   = scratch + OFF_Z;
    __nv_bfloat16* xHi   = (__nv_bfloat16*)(scratch + OFF_XHI);
    __nv_bfloat16* xLo   = (__nv_bfloat16*)(scratch + OFF_XLO);
    __nv_bfloat16* winHi = (__nv_bfloat16*)(scratch + OFF_WINHI);
    __nv_bfloat16* winLo = (__nv_bfloat16*)(scratch + OFF_WINLO);
    __nv_bfloat16* apHi  = (__nv_bfloat16*)(scratch + OFF_APHI);
    __nv_bfloat16* apLo  = (__nv_bfloat16*)(scratch + OFF_APLO);
    __nv_bfloat16* mtHi  = (__nv_bfloat16*)(scratch + OFF_MTHI);
    __nv_bfloat16* mtLo  = (__nv_bfloat16*)(scratch + OFF_MTLO);
    __nv_bfloat16* zHi   = (__nv_bfloat16*)(scratch + OFF_ZHI);
    __nv_bfloat16* zLo   = (__nv_bfloat16*)(scratch + OFF_ZLO);
    __nv_bfloat16* cmHi  = (__nv_bfloat16*)(scratch + OFF_CMHI);
    __nv_bfloat16* cmLo  = (__nv_bfloat16*)(scratch + OFF_CMLO);

    // 1. A'[512,2048] as bf16 hi/lo; W_in -> hi/lo
    build_aprime_bf16<<<(NPROJ * DI) / 256, 256>>>(W_x, W_dt, conv_w, apHi, apLo);
    f32_to_bf16x2<<<(DI * DM + 255) / 256, 256>>>(W_in, winHi, winLo, DI * DM);

    // 2. M[512,1024] = A' @ W_in  (bf16x3, split-K 8)
    gemm_bf16x3<<<dim3(DM / 128, NPROJ / 128, 8), 256>>>(
        apHi, apLo, winHi, winLo, Mpart, nullptr, NPROJ, DM, DI, DI / 8);
    reduce_kernel<<<(NPROJ * DM) / 256, 256>>>(Mpart, Mfull, NPROJ * DM, 8);

    // 3. Mt = M^T, then -> hi/lo ; x -> hi/lo
    transpose_kernel<<<dim3(DM / 32, NPROJ / 32), dim3(32, 8)>>>(Mfull, Mt, NPROJ, DM);
    f32_to_bf16x2<<<(DM * NPROJ + 255) / 256, 256>>>(Mt, mtHi, mtLo, DM * NPROJ);
    f32_to_bf16x2<<<(BL * DM + 255) / 256, 256>>>(x, xHi, xLo, BL * DM);

    // 4. Main GEMM: G[8192,512] = X @ Mt  (bf16x3)
    gemm_bf16x3<<<dim3(NPROJ / 128, BL / 128, 1), 256>>>(
        xHi, xLo, mtHi, mtLo, G, nullptr, BL, NPROJ, DM, DM);

    // 5. Cm[64,1024] = D_mat @ W_out^T  (small; fp32 split-K)
    transpose_kernel<<<dim3(DI / 32, DM / 32), dim3(32, 8)>>>(W_out, WoT, DM, DI);
    sgemm128<<<dim3(DM / 128, 1, 16), 256>>>(
        D_mat, WoT, Cpart, nullptr, DS, DM, DI, DI / 16);
    reduce_kernel<<<(DS * DM) / 256, 256>>>(Cpart, Cm, DS * DM, 16);

    // 6. bias terms
    bias_kernel<<<80, 256>>>(W_x, W_dt, b_x, b_dt, conv_w, conv_b, b_in, bias0, tb);

    // 7. tap combine + SSM elementwise -> dA, dBx
    combine_kernel<<<(BL * DS) / 256, 256>>>(G, bias0, tb, A_log, dAarr, dBxarr);

    // 8. chunked parallel scan -> Z[8192,64]
    scan_phase1<<<dim3(BB, NCHUNK), DS>>>(dAarr, dBxarr, chA, chB);
    scan_phase2<<<1, BB * DS>>>(chA, chB, zinit);
    scan_phase3<<<dim3(BB, NCHUNK), DS>>>(dAarr, dBxarr, zinit, Zarr);

    // 9. out[8192,1024] = Z @ Cm + b_out  (bf16x3)
    f32_to_bf16x2<<<(BL * DS + 255) / 256, 256>>>(Zarr, zHi, zLo, BL * DS);
    f32_to_bf16x2<<<(DS * DM + 255) / 256, 256>>>(Cm, cmHi, cmLo, DS * DM);
    gemm_bf16x3<<<dim3(DM / 128, BL / 128, 1), 256>>>(
        zHi, zLo, cmHi, cmLo, out, b_out, BL, DM, DS, DS);
}